// round 9
// baseline (speedup 1.0000x reference)
#include <cuda_runtime.h>
#include <cooperative_groups.h>

namespace cg = cooperative_groups;

#define BB 512
#define DD 512
#define NN 196
#define NP 224        // n padded to 7*32
#define DH 256        // d-half per cluster CTA

// scratch (no cudaMalloc allowed)
__device__ float g_mem[BB * DD];
__device__ float g_v1[BB * DD];
__device__ float g_v2[BB * DD];

// ---------------------------------------------------------------------------
// Fused GEMM:  mem = ms @ Wm^T + bm          (f-tiles 0..7)
//              v   = (ctrl*Wattn) @ Wcat     (f-tiles 8..23 -> v1 | v2)
// 32(b) x 64(f) tile, 256 threads, 2x4 per thread, k-tile 16, register
// prefetch of the next k-tile overlapping compute. grid 24x16 = 384.
// ---------------------------------------------------------------------------
__global__ __launch_bounds__(256) void gemm_kernel(
    const float* __restrict__ ms, const float* __restrict__ Wm,
    const float* __restrict__ bm, const float* __restrict__ ctrl,
    const float* __restrict__ Wattn, const float* __restrict__ Wcat,
    float* __restrict__ memo, float* __restrict__ v1, float* __restrict__ v2)
{
    __shared__ float As[16][36];
    __shared__ float Bs[16][68];
    const int t = threadIdx.x;
    const int tx = t & 15, ty = t >> 4;           // tx: f/4, ty: b/2
    const int b0 = blockIdx.y * 32;
    const bool is_mem = (blockIdx.x < 8);
    const int f0 = is_mem ? blockIdx.x * 64 : (blockIdx.x - 8) * 64;
    float acc[2][4] = {};

    // ---- per-thread load coordinates ----
    const int arow = t >> 2, akq = (t & 3) << 2;          // A: threads 0..127
    const int wfr  = t >> 2, wkk = (t & 3) << 2;          // Wm: all 256
    const int ckk  = t >> 4, cfq = (t & 15) << 2;         // Wcat: all 256

    float4 aP, bP;
    // prologue: prefetch k-tile 0
    {
        if (t < 128) {
            if (is_mem) {
                aP = *(const float4*)(ms + (b0 + arow) * DD + akq);
            } else {
                float4 c4 = *(const float4*)(ctrl + (b0 + arow) * DD + akq);
                float4 w4 = *(const float4*)(Wattn + akq);
                aP = make_float4(c4.x * w4.x, c4.y * w4.y, c4.z * w4.z, c4.w * w4.w);
            }
        }
        if (is_mem) bP = *(const float4*)(Wm + (f0 + wfr) * DD + wkk);
        else        bP = *(const float4*)(Wcat + (size_t)ckk * (2 * DD) + f0 + cfq);
    }

    for (int k0 = 0; k0 < DD; k0 += 16) {
        // ---- store prefetched tile ----
        if (t < 128) {
            As[akq + 0][arow] = aP.x; As[akq + 1][arow] = aP.y;
            As[akq + 2][arow] = aP.z; As[akq + 3][arow] = aP.w;
        }
        if (is_mem) {
            Bs[wkk + 0][wfr] = bP.x; Bs[wkk + 1][wfr] = bP.y;
            Bs[wkk + 2][wfr] = bP.z; Bs[wkk + 3][wfr] = bP.w;
        } else {
            *(float4*)&Bs[ckk][cfq] = bP;
        }
        __syncthreads();

        // ---- prefetch next tile (overlaps compute) ----
        const int kn = k0 + 16;
        if (kn < DD) {
            if (t < 128) {
                if (is_mem) {
                    aP = *(const float4*)(ms + (b0 + arow) * DD + kn + akq);
                } else {
                    float4 c4 = *(const float4*)(ctrl + (b0 + arow) * DD + kn + akq);
                    float4 w4 = *(const float4*)(Wattn + kn + akq);
                    aP = make_float4(c4.x * w4.x, c4.y * w4.y, c4.z * w4.z, c4.w * w4.w);
                }
            }
            if (is_mem) bP = *(const float4*)(Wm + (f0 + wfr) * DD + kn + wkk);
            else        bP = *(const float4*)(Wcat + (size_t)(kn + ckk) * (2 * DD) + f0 + cfq);
        }

        // ---- compute ----
#pragma unroll
        for (int k = 0; k < 16; k++) {
            float a0 = As[k][ty * 2], a1 = As[k][ty * 2 + 1];
            float4 b = *(const float4*)&Bs[k][tx * 4];
            acc[0][0] += a0 * b.x; acc[0][1] += a0 * b.y;
            acc[0][2] += a0 * b.z; acc[0][3] += a0 * b.w;
            acc[1][0] += a1 * b.x; acc[1][1] += a1 * b.y;
            acc[1][2] += a1 * b.z; acc[1][3] += a1 * b.w;
        }
        __syncthreads();
    }

#pragma unroll
    for (int r = 0; r < 2; r++) {
        int b = b0 + ty * 2 + r;
#pragma unroll
        for (int c = 0; c < 4; c++) {
            int f = f0 + tx * 4 + c;
            if (is_mem)      memo[b * DD + f] = acc[r][c] + bm[f];
            else if (f < DD) v1[b * DD + f] = acc[r][c];
            else             v2[b * DD + (f - DD)] = acc[r][c];
        }
    }
}

// ---------------------------------------------------------------------------
// Cluster attention read: 2 CTAs per batch (cluster), each owns a d-half.
// Phase A: stream kbp half (discard) + kb half (cache in smem), partial
// logits in registers. Cross-CTA logit reduce via DSMEM. Softmax per CTA.
// Phase C: weighted sum entirely from smem — kb is read from DRAM ONCE.
// ---------------------------------------------------------------------------
__global__ __launch_bounds__(512) __cluster_dims__(2, 1, 1)
void attn_kernel(
    const float* __restrict__ kb, const float* __restrict__ kbp,
    const float* __restrict__ memo, const float* __restrict__ v1,
    const float* __restrict__ v2, float* __restrict__ out)
{
    extern __shared__ float smf[];
    float* skb  = smf;                 // [DH * NN] cached kb half
    float* su1  = skb + DH * NN;       // [DH]
    float* su2  = su1 + DH;            // [DH]
    float* part = su2 + DH;            // [16 * NP] per-warp partials -> row 0 = CTA total
    float* sw   = part + 16 * NP;      // [NP] softmax weights

    cg::cluster_group cluster = cg::this_cluster();
    const unsigned rank = cluster.block_rank();
    const int b = blockIdx.x >> 1;
    const int d_base = rank * DH;
    const int tid = threadIdx.x;
    const int w = tid >> 5, lane = tid & 31;

    const float* kbB = kb  + (size_t)b * DD * NN + (size_t)d_base * NN;
    const float* kpB = kbp + (size_t)b * DD * NN + (size_t)d_base * NN;

    // u vectors for my d-half: u1 = v1*mem, u2 = v2
    if (tid < DH) {
        su1[tid] = v1[b * DD + d_base + tid] * memo[b * DD + d_base + tid];
        su2[tid] = v2[b * DD + d_base + tid];
    }
    __syncthreads();

    // ---- Phase A: warp w owns local rows [w*16, w*16+16) ----
    {
        float acc[7] = {};
        const int r0 = w * 16;
#pragma unroll 2
        for (int dd = 0; dd < 16; dd++) {
            const int row = r0 + dd;
            const float a1 = su1[row], a2 = su2[row];
            const float* p0 = kpB + (size_t)row * NN;
            const float* k0 = kbB + (size_t)row * NN;
            float* dst = skb + row * NN;
#pragma unroll
            for (int j = 0; j < 6; j++) {
                const int n = lane + 32 * j;
                const float kv = k0[n];
                dst[n] = kv;
                acc[j] += a1 * p0[n] + a2 * kv;
            }
            if (lane < 4) {
                const int n = 192 + lane;
                const float kv = k0[n];
                dst[n] = kv;
                acc[6] += a1 * p0[n] + a2 * kv;
            }
        }
#pragma unroll
        for (int j = 0; j < 7; j++) part[w * NP + lane + 32 * j] = acc[j];
    }
    __syncthreads();

    // ---- reduce 16 warp-partials -> CTA partial in part[0..NP) ----
    if (tid < NP) {
        float s = 0.f;
#pragma unroll
        for (int w2 = 0; w2 < 16; w2++) s += part[w2 * NP + tid];
        part[tid] = s;
    }
    // sync1: my partial visible cluster-wide
    cluster.sync();

    // ---- add peer partial via DSMEM ----
    {
        const float* peer = cluster.map_shared_rank(part, rank ^ 1);
        if (tid < NP) {
            float tot = part[tid] + peer[tid];
            sw[tid] = (tid < NN) ? tot : -1e30f;
        }
    }
    // sync2: both CTAs done reading peer smem
    cluster.sync();

    // ---- softmax (warp 0), broadcast via sw ----
    if (w == 0) {
        float l[7];
#pragma unroll
        for (int j = 0; j < 7; j++) l[j] = sw[lane + 32 * j];
        float m = l[0];
#pragma unroll
        for (int j = 1; j < 7; j++) m = fmaxf(m, l[j]);
#pragma unroll
        for (int off = 16; off; off >>= 1)
            m = fmaxf(m, __shfl_xor_sync(0xffffffffu, m, off));
        float e[7], S = 0.f;
#pragma unroll
        for (int j = 0; j < 7; j++) { e[j] = __expf(l[j] - m); S += e[j]; }
#pragma unroll
        for (int off = 16; off; off >>= 1)
            S += __shfl_xor_sync(0xffffffffu, S, off);
        const float inv = 1.f / S;
#pragma unroll
        for (int j = 0; j < 7; j++) sw[lane + 32 * j] = e[j] * inv;
    }
    __syncthreads();

    // ---- Phase C: out from smem-cached kb ----
    {
        float swr[7];
#pragma unroll
        for (int j = 0; j < 7; j++) swr[j] = sw[lane + 32 * j];
        const int r0 = w * 16;
#pragma unroll 2
        for (int dd = 0; dd < 16; dd += 2) {
            const int row = r0 + dd;
            const float* k0 = skb + row * NN;
            float s0 = 0.f, s1 = 0.f;
#pragma unroll
            for (int j = 0; j < 6; j++) {
                const int n = lane + 32 * j;
                s0 += swr[j] * k0[n];
                s1 += swr[j] * k0[NN + n];
            }
            if (lane < 4) {
                s0 += swr[6] * k0[192 + lane];
                s1 += swr[6] * k0[NN + 192 + lane];
            }
#pragma unroll
            for (int off = 16; off; off >>= 1) {
                s0 += __shfl_xor_sync(0xffffffffu, s0, off);
                s1 += __shfl_xor_sync(0xffffffffu, s1, off);
            }
            if (!lane) *(float2*)(out + b * DD + d_base + row) = make_float2(s0, s1);
        }
    }
}

// ---------------------------------------------------------------------------
extern "C" void kernel_launch(void* const* d_in, const int* in_sizes, int n_in,
                              void* d_out, int out_size)
{
    const float* memory_state   = (const float*)d_in[0];  // [B, D]
    const float* knowledge_base = (const float*)d_in[1];  // [B, D, N]
    const float* ctrl_state     = (const float*)d_in[2];  // [B, D]
    const float* kb_proj        = (const float*)d_in[3];  // [B, D, N]
    const float* W_mem          = (const float*)d_in[4];  // [D, D]
    const float* b_mem          = (const float*)d_in[5];  // [D]
    const float* W_cat          = (const float*)d_in[6];  // [D, 2D]
    // d_in[7] = b_cat, d_in[9] = b_attn: softmax-invariant, dropped exactly
    const float* W_attn         = (const float*)d_in[8];  // [1, D]
    float* out = (float*)d_out;                           // [B, D]

    float* memo; cudaGetSymbolAddress((void**)&memo, g_mem);
    float* v1;   cudaGetSymbolAddress((void**)&v1,  g_v1);
    float* v2;   cudaGetSymbolAddress((void**)&v2,  g_v2);

    const int smem_bytes = (DH * NN + 2 * DH + 16 * NP + NP) * 4;  // ~213 KB
    cudaFuncSetAttribute(attn_kernel, cudaFuncAttributeMaxDynamicSharedMemorySize,
                         smem_bytes);

    gemm_kernel<<<dim3(24, 16), 256>>>(memory_state, W_mem, b_mem,
                                       ctrl_state, W_attn, W_cat, memo, v1, v2);
    attn_kernel<<<2 * BB, 512, smem_bytes>>>(knowledge_base, kb_proj,
                                             memo, v1, v2, out);
}

// round 10
// speedup vs baseline: 1.0881x; 1.0881x over previous
#include <cuda_runtime.h>

#define BB 512
#define DD 512
#define NN 196
#define NP 224   // n padded to 7*32

// scratch (no cudaMalloc allowed)
__device__ float g_mem[BB * DD];
__device__ float g_v1[BB * DD];
__device__ float g_v2[BB * DD];

// ---------------------------------------------------------------------------
// Fused GEMM:  mem = ms @ Wm^T + bm          (f-tiles 0..7)
//              v   = (ctrl*Wattn) @ Wcat     (f-tiles 8..23 -> v1 | v2)
// 64(b) x 64(f) tile, 256 threads, 4x4 per thread, k-tile 16, register
// prefetch of next k-tile. grid 24 x 8 = 192.
// ---------------------------------------------------------------------------
__global__ __launch_bounds__(256) void gemm_kernel(
    const float* __restrict__ ms, const float* __restrict__ Wm,
    const float* __restrict__ bm, const float* __restrict__ ctrl,
    const float* __restrict__ Wattn, const float* __restrict__ Wcat,
    float* __restrict__ memo, float* __restrict__ v1, float* __restrict__ v2)
{
    __shared__ float As[16][68];
    __shared__ float Bs[16][68];
    const int t = threadIdx.x;
    const int tx = t & 15, ty = t >> 4;
    const int b0 = blockIdx.y * 64;
    const bool is_mem = (blockIdx.x < 8);
    const int f0 = is_mem ? blockIdx.x * 64 : (blockIdx.x - 8) * 64;
    const int arow = t >> 2, akq = (t & 3) << 2;   // A / Wm loads (64 x 16)
    const int ckk = t >> 4, cfq = (t & 15) << 2;   // Wcat loads (16 x 64)
    float acc[4][4] = {};

    float4 aP, bP;
    // prologue: prefetch k-tile 0
    {
        if (is_mem) {
            aP = *(const float4*)(ms + (b0 + arow) * DD + akq);
            bP = *(const float4*)(Wm + (f0 + arow) * DD + akq);
        } else {
            float4 c4 = *(const float4*)(ctrl + (b0 + arow) * DD + akq);
            float4 w4 = *(const float4*)(Wattn + akq);
            aP = make_float4(c4.x * w4.x, c4.y * w4.y, c4.z * w4.z, c4.w * w4.w);
            bP = *(const float4*)(Wcat + (size_t)ckk * (2 * DD) + f0 + cfq);
        }
    }

    for (int k0 = 0; k0 < DD; k0 += 16) {
        // ---- store prefetched tile (A and Wm transposed to [k][row]) ----
        As[akq + 0][arow] = aP.x; As[akq + 1][arow] = aP.y;
        As[akq + 2][arow] = aP.z; As[akq + 3][arow] = aP.w;
        if (is_mem) {
            Bs[akq + 0][arow] = bP.x; Bs[akq + 1][arow] = bP.y;
            Bs[akq + 2][arow] = bP.z; Bs[akq + 3][arow] = bP.w;
        } else {
            *(float4*)&Bs[ckk][cfq] = bP;
        }
        __syncthreads();

        // ---- prefetch next tile (overlaps compute) ----
        const int kn = k0 + 16;
        if (kn < DD) {
            if (is_mem) {
                aP = *(const float4*)(ms + (b0 + arow) * DD + kn + akq);
                bP = *(const float4*)(Wm + (f0 + arow) * DD + kn + akq);
            } else {
                float4 c4 = *(const float4*)(ctrl + (b0 + arow) * DD + kn + akq);
                float4 w4 = *(const float4*)(Wattn + kn + akq);
                aP = make_float4(c4.x * w4.x, c4.y * w4.y, c4.z * w4.z, c4.w * w4.w);
                bP = *(const float4*)(Wcat + (size_t)(kn + ckk) * (2 * DD) + f0 + cfq);
            }
        }

        // ---- compute 4x4 ----
#pragma unroll
        for (int k = 0; k < 16; k++) {
            float4 a = *(const float4*)&As[k][ty * 4];
            float4 b = *(const float4*)&Bs[k][tx * 4];
            float aa[4] = {a.x, a.y, a.z, a.w};
            float bb[4] = {b.x, b.y, b.z, b.w};
#pragma unroll
            for (int r = 0; r < 4; r++)
#pragma unroll
                for (int c = 0; c < 4; c++) acc[r][c] += aa[r] * bb[c];
        }
        __syncthreads();
    }

#pragma unroll
    for (int r = 0; r < 4; r++) {
        int b = b0 + ty * 4 + r;
#pragma unroll
        for (int c = 0; c < 4; c++) {
            int f = f0 + tx * 4 + c;
            if (is_mem)      memo[b * DD + f] = acc[r][c] + bm[f];
            else if (f < DD) v1[b * DD + f] = acc[r][c];
            else             v2[b * DD + (f - DD)] = acc[r][c];
        }
    }
}

// ---------------------------------------------------------------------------
// Two-pass attention read. One CTA per batch, 512 threads (16 warps).
// Phase A: partial logits in registers (coalesced streaming, no syncs).
// Reduce + softmax once per batch. Phase C: weighted sum, re-reads kb.
// 4 __syncthreads per batch. ~20 KB smem -> ~3.5 CTAs/SM, ~55 warps/SM.
// ---------------------------------------------------------------------------
__global__ __launch_bounds__(512) void attn_kernel(
    const float* __restrict__ kb, const float* __restrict__ kbp,
    const float* __restrict__ memo, const float* __restrict__ v1,
    const float* __restrict__ v2, float* __restrict__ out)
{
    __shared__ float su1[DD];
    __shared__ float su2[DD];
    __shared__ float part[16 * NP];
    __shared__ float sw[NP];

    const int b = blockIdx.x;
    const int tid = threadIdx.x;
    const int w = tid >> 5, lane = tid & 31;
    const float* kbB = kb  + (size_t)b * DD * NN;
    const float* kpB = kbp + (size_t)b * DD * NN;

    // u1 = v1*mem, u2 = v2
    su1[tid] = v1[b * DD + tid] * memo[b * DD + tid];
    su2[tid] = v2[b * DD + tid];
    __syncthreads();

    // ---- Phase A: partial logits. warp w owns d in [w*32, w*32+32). ----
    {
        float acc[7] = {};
        const int d0 = w * 32;
#pragma unroll 2
        for (int dd = 0; dd < 32; dd += 2) {
            const int d = d0 + dd;
            const float a1 = su1[d],     a2 = su2[d];
            const float c1 = su1[d + 1], c2 = su2[d + 1];
            const float* p0 = kpB + (size_t)d * NN;
            const float* k0 = kbB + (size_t)d * NN;
#pragma unroll
            for (int j = 0; j < 6; j++) {
                const int n = lane + 32 * j;
                acc[j] += a1 * __ldcs(p0 + n)      + a2 * k0[n]
                        + c1 * __ldcs(p0 + NN + n) + c2 * k0[NN + n];
            }
            if (lane < 4) {
                const int n = 192 + lane;
                acc[6] += a1 * __ldcs(p0 + n)      + a2 * k0[n]
                        + c1 * __ldcs(p0 + NN + n) + c2 * k0[NN + n];
            }
        }
#pragma unroll
        for (int j = 0; j < 7; j++) part[w * NP + lane + 32 * j] = acc[j];
    }
    __syncthreads();

    // ---- reduce partials across 16 warps ----
    if (tid < NP) {
        float s = 0.f;
#pragma unroll
        for (int w2 = 0; w2 < 16; w2++) s += part[w2 * NP + tid];
        sw[tid] = (tid < NN) ? s : -1e30f;
    }
    __syncthreads();

    // ---- softmax (warp 0): sw[n] = exp(l-m)/S ----
    if (w == 0) {
        float l[7];
#pragma unroll
        for (int j = 0; j < 7; j++) l[j] = sw[lane + 32 * j];
        float m = l[0];
#pragma unroll
        for (int j = 1; j < 7; j++) m = fmaxf(m, l[j]);
#pragma unroll
        for (int off = 16; off; off >>= 1)
            m = fmaxf(m, __shfl_xor_sync(0xffffffffu, m, off));
        float e[7], S = 0.f;
#pragma unroll
        for (int j = 0; j < 7; j++) { e[j] = __expf(l[j] - m); S += e[j]; }
#pragma unroll
        for (int off = 16; off; off >>= 1)
            S += __shfl_xor_sync(0xffffffffu, S, off);
        const float inv = 1.f / S;
#pragma unroll
        for (int j = 0; j < 7; j++) sw[lane + 32 * j] = e[j] * inv;
    }
    __syncthreads();

    // ---- Phase C: out[d] = sum_n sw[n]*kb[d,n]. Same warp/d mapping. ----
    {
        float swr[7];
#pragma unroll
        for (int j = 0; j < 7; j++) swr[j] = sw[lane + 32 * j];
        const int d0 = w * 32;
#pragma unroll 2
        for (int dd = 0; dd < 32; dd += 2) {
            const int d = d0 + dd;
            const float* k0 = kbB + (size_t)d * NN;
            float s0 = 0.f, s1 = 0.f;
#pragma unroll
            for (int j = 0; j < 6; j++) {
                const int n = lane + 32 * j;
                s0 += swr[j] * k0[n];
                s1 += swr[j] * k0[NN + n];
            }
            if (lane < 4) {
                s0 += swr[6] * k0[192 + lane];
                s1 += swr[6] * k0[NN + 192 + lane];
            }
#pragma unroll
            for (int off = 16; off; off >>= 1) {
                s0 += __shfl_xor_sync(0xffffffffu, s0, off);
                s1 += __shfl_xor_sync(0xffffffffu, s1, off);
            }
            if (!lane) *(float2*)(out + b * DD + d) = make_float2(s0, s1);
        }
    }
}

// ---------------------------------------------------------------------------
extern "C" void kernel_launch(void* const* d_in, const int* in_sizes, int n_in,
                              void* d_out, int out_size)
{
    const float* memory_state   = (const float*)d_in[0];  // [B, D]
    const float* knowledge_base = (const float*)d_in[1];  // [B, D, N]
    const float* ctrl_state     = (const float*)d_in[2];  // [B, D]
    const float* kb_proj        = (const float*)d_in[3];  // [B, D, N]
    const float* W_mem          = (const float*)d_in[4];  // [D, D]
    const float* b_mem          = (const float*)d_in[5];  // [D]
    const float* W_cat          = (const float*)d_in[6];  // [D, 2D]
    // d_in[7] = b_cat, d_in[9] = b_attn: softmax-invariant, dropped exactly
    const float* W_attn         = (const float*)d_in[8];  // [1, D]
    float* out = (float*)d_out;                           // [B, D]

    float* memo; cudaGetSymbolAddress((void**)&memo, g_mem);
    float* v1;   cudaGetSymbolAddress((void**)&v1,  g_v1);
    float* v2;   cudaGetSymbolAddress((void**)&v2,  g_v2);

    gemm_kernel<<<dim3(24, 8), 256>>>(memory_state, W_mem, b_mem,
                                      ctrl_state, W_attn, W_cat, memo, v1, v2);
    attn_kernel<<<BB, 512>>>(knowledge_base, kb_proj, memo, v1, v2, out);
}

// round 12
// speedup vs baseline: 1.1407x; 1.0483x over previous
#include <cuda_runtime.h>

#define BB 512
#define DD 512
#define NN 196
#define NP 224   // n padded to 7*32

// scratch (no cudaMalloc allowed)
__device__ float g_mem[BB * DD];
__device__ float g_v1[BB * DD];
__device__ float g_v2[BB * DD];

// packed fp32x2 helpers (sm_103a FFMA2 — PTX-only pattern)
#define DUP_F32X2(d, s) \
    asm("mov.b64 %0, {%1, %1};" : "=l"(d) : "f"(s))
#define FMA_F32X2(acc, a, b) \
    asm("fma.rn.f32x2 %0, %1, %2, %0;" : "+l"(acc) : "l"(a), "l"(b))
#define UNPACK_F32X2(lo, hi, s) \
    asm("mov.b64 {%0, %1}, %2;" : "=f"(lo), "=f"(hi) : "l"(s))

// ---------------------------------------------------------------------------
// Fused GEMM:  mem = ms @ Wm^T + bm          (f-tiles 0..7)
//              v   = (ctrl*Wattn) @ Wcat     (f-tiles 8..23 -> v1 | v2)
// 64(b) x 64(f) tile, 256 threads, 4x4 per thread via packed FFMA2
// (row-pairs from LDS.64, B scalars duplicated), k-tile 16, register
// prefetch of next k-tile. grid 24 x 8 = 192.
// ---------------------------------------------------------------------------
__global__ __launch_bounds__(256) void gemm_kernel(
    const float* __restrict__ ms, const float* __restrict__ Wm,
    const float* __restrict__ bm, const float* __restrict__ ctrl,
    const float* __restrict__ Wattn, const float* __restrict__ Wcat,
    float* __restrict__ memo, float* __restrict__ v1, float* __restrict__ v2)
{
    __shared__ float As[16][68];
    __shared__ float Bs[16][68];
    const int t = threadIdx.x;
    const int tx = t & 15, ty = t >> 4;
    const int b0 = blockIdx.y * 64;
    const bool is_mem = (blockIdx.x < 8);
    const int f0 = is_mem ? blockIdx.x * 64 : (blockIdx.x - 8) * 64;
    const int arow = t >> 2, akq = (t & 3) << 2;   // A / Wm loads (64 x 16)
    const int ckk = t >> 4, cfq = (t & 15) << 2;   // Wcat loads (16 x 64)

    // packed accumulators: acc01[c] holds rows (ty*4, ty*4+1), acc23[c] rows (+2,+3)
    unsigned long long acc01[4] = {}, acc23[4] = {};

    float4 aP, bP;
    // prologue: prefetch k-tile 0
    {
        if (is_mem) {
            aP = *(const float4*)(ms + (b0 + arow) * DD + akq);
            bP = *(const float4*)(Wm + (f0 + arow) * DD + akq);
        } else {
            float4 c4 = *(const float4*)(ctrl + (b0 + arow) * DD + akq);
            float4 w4 = *(const float4*)(Wattn + akq);
            aP = make_float4(c4.x * w4.x, c4.y * w4.y, c4.z * w4.z, c4.w * w4.w);
            bP = *(const float4*)(Wcat + (size_t)ckk * (2 * DD) + f0 + cfq);
        }
    }

    for (int k0 = 0; k0 < DD; k0 += 16) {
        // ---- store prefetched tile (A and Wm transposed to [k][row]) ----
        As[akq + 0][arow] = aP.x; As[akq + 1][arow] = aP.y;
        As[akq + 2][arow] = aP.z; As[akq + 3][arow] = aP.w;
        if (is_mem) {
            Bs[akq + 0][arow] = bP.x; Bs[akq + 1][arow] = bP.y;
            Bs[akq + 2][arow] = bP.z; Bs[akq + 3][arow] = bP.w;
        } else {
            *(float4*)&Bs[ckk][cfq] = bP;
        }
        __syncthreads();

        // ---- prefetch next tile (overlaps compute) ----
        const int kn = k0 + 16;
        if (kn < DD) {
            if (is_mem) {
                aP = *(const float4*)(ms + (b0 + arow) * DD + kn + akq);
                bP = *(const float4*)(Wm + (f0 + arow) * DD + kn + akq);
            } else {
                float4 c4 = *(const float4*)(ctrl + (b0 + arow) * DD + kn + akq);
                float4 w4 = *(const float4*)(Wattn + kn + akq);
                aP = make_float4(c4.x * w4.x, c4.y * w4.y, c4.z * w4.z, c4.w * w4.w);
                bP = *(const float4*)(Wcat + (size_t)(kn + ckk) * (2 * DD) + f0 + cfq);
            }
        }

        // ---- compute 4x4 as 8 packed FFMA2 per k ----
#pragma unroll
        for (int k = 0; k < 16; k++) {
            const unsigned long long a01 =
                *(const unsigned long long*)&As[k][ty * 4];
            const unsigned long long a23 =
                *(const unsigned long long*)&As[k][ty * 4 + 2];
            const float4 b = *(const float4*)&Bs[k][tx * 4];
            unsigned long long bd0, bd1, bd2, bd3;
            DUP_F32X2(bd0, b.x); DUP_F32X2(bd1, b.y);
            DUP_F32X2(bd2, b.z); DUP_F32X2(bd3, b.w);
            FMA_F32X2(acc01[0], a01, bd0); FMA_F32X2(acc23[0], a23, bd0);
            FMA_F32X2(acc01[1], a01, bd1); FMA_F32X2(acc23[1], a23, bd1);
            FMA_F32X2(acc01[2], a01, bd2); FMA_F32X2(acc23[2], a23, bd2);
            FMA_F32X2(acc01[3], a01, bd3); FMA_F32X2(acc23[3], a23, bd3);
        }
        __syncthreads();
    }

    // ---- epilogue: unpack and store ----
#pragma unroll
    for (int c = 0; c < 4; c++) {
        const int f = f0 + tx * 4 + c;
        float r0, r1, r2, r3;
        UNPACK_F32X2(r0, r1, acc01[c]);
        UNPACK_F32X2(r2, r3, acc23[c]);
        float vals[4] = {r0, r1, r2, r3};
#pragma unroll
        for (int r = 0; r < 4; r++) {
            const int b = b0 + ty * 4 + r;
            if (is_mem)      memo[b * DD + f] = vals[r] + bm[f];
            else if (f < DD) v1[b * DD + f] = vals[r];
            else             v2[b * DD + (f - DD)] = vals[r];
        }
    }
}

// ---------------------------------------------------------------------------
// Two-pass attention read (R8 config — known 125.4us / 62.7% DRAM).
// One CTA per batch, 256 threads (8 warps).
// Phase A: partial logits in registers (coalesced streaming, no syncs).
// Reduce + softmax once per batch. Phase C: weighted sum, re-reads kb.
// Only 4 __syncthreads per batch.
// ---------------------------------------------------------------------------
__global__ __launch_bounds__(256) void attn_kernel(
    const float* __restrict__ kb, const float* __restrict__ kbp,
    const float* __restrict__ memo, const float* __restrict__ v1,
    const float* __restrict__ v2, float* __restrict__ out)
{
    __shared__ float su1[DD];
    __shared__ float su2[DD];
    __shared__ float part[8 * NP];
    __shared__ float sw[NP];

    const int b = blockIdx.x;
    const int tid = threadIdx.x;
    const int w = tid >> 5, lane = tid & 31;
    const float* kbB = kb  + (size_t)b * DD * NN;
    const float* kpB = kbp + (size_t)b * DD * NN;

    // u1 = v1*mem, u2 = v2
    su1[tid]       = v1[b * DD + tid]       * memo[b * DD + tid];
    su1[tid + 256] = v1[b * DD + tid + 256] * memo[b * DD + tid + 256];
    su2[tid]       = v2[b * DD + tid];
    su2[tid + 256] = v2[b * DD + tid + 256];
    __syncthreads();

    // ---- Phase A: partial logits. warp w owns d in [w*64, w*64+64). ----
    {
        float acc[7] = {};
        const int d0 = w * 64;
#pragma unroll 2
        for (int dd = 0; dd < 64; dd += 2) {
            const int d = d0 + dd;
            const float a1 = su1[d],     a2 = su2[d];
            const float c1 = su1[d + 1], c2 = su2[d + 1];
            const float* p0 = kpB + (size_t)d * NN;
            const float* k0 = kbB + (size_t)d * NN;
#pragma unroll
            for (int j = 0; j < 6; j++) {
                const int n = lane + 32 * j;
                acc[j] += a1 * p0[n]      + a2 * k0[n]
                        + c1 * p0[NN + n] + c2 * k0[NN + n];
            }
            if (lane < 4) {
                const int n = 192 + lane;
                acc[6] += a1 * p0[n]      + a2 * k0[n]
                        + c1 * p0[NN + n] + c2 * k0[NN + n];
            }
        }
#pragma unroll
        for (int j = 0; j < 7; j++) part[w * NP + lane + 32 * j] = acc[j];
    }
    __syncthreads();

    // ---- reduce partials across warps ----
    if (tid < NP) {
        float s = 0.f;
#pragma unroll
        for (int w2 = 0; w2 < 8; w2++) s += part[w2 * NP + tid];
        sw[tid] = (tid < NN) ? s : -1e30f;
    }
    __syncthreads();

    // ---- softmax (warp 0): sw[n] = exp(l-m)/S ----
    if (w == 0) {
        float l[7];
#pragma unroll
        for (int j = 0; j < 7; j++) l[j] = sw[lane + 32 * j];
        float m = l[0];
#pragma unroll
        for (int j = 1; j < 7; j++) m = fmaxf(m, l[j]);
#pragma unroll
        for (int off = 16; off; off >>= 1)
            m = fmaxf(m, __shfl_xor_sync(0xffffffffu, m, off));
        float e[7], S = 0.f;
#pragma unroll
        for (int j = 0; j < 7; j++) { e[j] = __expf(l[j] - m); S += e[j]; }
#pragma unroll
        for (int off = 16; off; off >>= 1)
            S += __shfl_xor_sync(0xffffffffu, S, off);
        const float inv = 1.f / S;
#pragma unroll
        for (int j = 0; j < 7; j++) sw[lane + 32 * j] = e[j] * inv;
    }
    __syncthreads();

    // ---- Phase C: out[d] = sum_n sw[n]*kb[d,n]. Same warp/d mapping. ----
    {
        float swr[7];
#pragma unroll
        for (int j = 0; j < 7; j++) swr[j] = sw[lane + 32 * j];
        const int d0 = w * 64;
#pragma unroll 2
        for (int dd = 0; dd < 64; dd += 2) {
            const int d = d0 + dd;
            const float* k0 = kbB + (size_t)d * NN;
            float s0 = 0.f, s1 = 0.f;
#pragma unroll
            for (int j = 0; j < 6; j++) {
                const int n = lane + 32 * j;
                s0 += swr[j] * k0[n];
                s1 += swr[j] * k0[NN + n];
            }
            if (lane < 4) {
                s0 += swr[6] * k0[192 + lane];
                s1 += swr[6] * k0[NN + 192 + lane];
            }
#pragma unroll
            for (int off = 16; off; off >>= 1) {
                s0 += __shfl_xor_sync(0xffffffffu, s0, off);
                s1 += __shfl_xor_sync(0xffffffffu, s1, off);
            }
            if (!lane) *(float2*)(out + b * DD + d) = make_float2(s0, s1);
        }
    }
}

// ---------------------------------------------------------------------------
extern "C" void kernel_launch(void* const* d_in, const int* in_sizes, int n_in,
                              void* d_out, int out_size)
{
    const float* memory_state   = (const float*)d_in[0];  // [B, D]
    const float* knowledge_base = (const float*)d_in[1];  // [B, D, N]
    const float* ctrl_state     = (const float*)d_in[2];  // [B, D]
    const float* kb_proj        = (const float*)d_in[3];  // [B, D, N]
    const float* W_mem          = (const float*)d_in[4];  // [D, D]
    const float* b_mem          = (const float*)d_in[5];  // [D]
    const float* W_cat          = (const float*)d_in[6];  // [D, 2D]
    // d_in[7] = b_cat, d_in[9] = b_attn: softmax-invariant, dropped exactly
    const float* W_attn         = (const float*)d_in[8];  // [1, D]
    float* out = (float*)d_out;                           // [B, D]

    float* memo; cudaGetSymbolAddress((void**)&memo, g_mem);
    float* v1;   cudaGetSymbolAddress((void**)&v1,  g_v1);
    float* v2;   cudaGetSymbolAddress((void**)&v2,  g_v2);

    gemm_kernel<<<dim3(24, 8), 256>>>(memory_state, W_mem, b_mem,
                                      ctrl_state, W_attn, W_cat, memo, v1, v2);
    attn_kernel<<<BB, 256>>>(knowledge_base, kb_proj, memo, v1, v2, out);
}